// round 13
// baseline (speedup 1.0000x reference)
#include <cuda_runtime.h>
#include <cuda_bf16.h>
#include <cuda_fp16.h>

#define R_ROWS 4
#define NROWS  (R_ROWS + 2)

template<int N> struct IC { static constexpr int value = N; };

// KAN 3x3 conv. Fully fused per-cell cubic: value_f(v) = silu(v)*bw[f] + spline_f(v)
// approximated per 0.4-wide cell by one cubic in u (silu part: interpolating cubic,
// err ~2e-5; spline part: exact). 31 cells cover v in [-6.2, 6.2); outer cells are
// silu-only. Eliminates silu + base FMAs from the mainloop entirely.
// Accumulation pair evals: a0,a1 fp32 + (a2,a3) half2; send evals: full fp32.
__global__ __launch_bounds__(128, 7)
void kan_conv_kernel(const float* __restrict__ x,
                     const float* __restrict__ bw,
                     const float* __restrict__ sw,
                     const float* __restrict__ ss,
                     float* __restrict__ out)
{
    __shared__ float4 scal[31 * 9];   // fused fp32 coeffs (a0,a1,a2,a3); also the send table
    __shared__ float4 pA01[31 * 3];   // even-pixel pair (f=3kh, 3kh+1): (a0A,a0B,a1A,a1B)
    __shared__ uint2  pA23[31 * 3];   // {h2(a2A,a2B), h2(a3A,a3B)}
    __shared__ float4 pB01[31 * 3];   // odd-pixel pair (f=3kh+1, 3kh+2)
    __shared__ uint2  pB23[31 * 3];
    __shared__ float  Zs[9];          // fused value at padding pixels (x=0)

    const int lane  = threadIdx.x & 31;
    const int warp  = threadIdx.x >> 5;
    const int img   = blockIdx.x >> 2;                  // 1024 blocks = 256 images x 4
    const int strip = ((blockIdx.x & 3) << 2) | warp;   // 0..15
    const int y0    = strip * R_ROWS;

    // ---- build fused per-cell cubics (31 cells x 9 features) ----
    for (int t = threadIdx.x; t < 31 * 9; t += 128) {
        const int J = t / 9, f = t - J * 9;
        const float bwf = __ldg(&bw[f]);
        const float v0  = 0.4f * J - 6.2f;              // cell start; v = v0 + 0.4*u

        // silu*bw cubic fit through u = 0, 1/3, 2/3, 1
        float s[4];
        #pragma unroll
        for (int k = 0; k < 4; k++) {
            float v = v0 + 0.4f * (k * (1.f / 3.f));
            s[k] = (v / (1.f + __expf(-v))) * bwf;
        }
        const float d1 = s[1] - s[0], d2 = s[2] - s[0], d3 = s[3] - s[0];
        float a0 = s[0];
        float a1 = 9.f * d1 - 4.5f * d2 + d3;
        float a2 = 13.5f * d1 - 0.5f * d3 - 4.f * a1;
        float a3 = d3 - a1 - a2;

        // spline part (exact) on in-grid cells J in [10,20], original cell j = J-10
        if (J >= 10 && J <= 20) {
            const int j = J - 10;
            float scale = __ldg(&ss[f]);
            float W[4];
            #pragma unroll
            for (int c = 0; c < 4; c++) {
                int bi = j + c - 3;
                W[c] = (bi >= 0 && bi < 8) ? __ldg(&sw[f * 8 + bi]) * scale : 0.f;
            }
            const float S = 1.f / 6.f;
            a0 += (W[0] + 4.f * W[1] + W[2]) * S;
            a1 += (W[2] - W[0]) * 0.5f;
            a2 += (W[0] - 2.f * W[1] + W[2]) * 0.5f;
            a3 += (W[3] - W[0] + 3.f * (W[1] - W[2])) * S;
        }
        scal[t] = make_float4(a0, a1, a2, a3);
        // padding pixel x=0 -> J=15, u=0.5
        if (J == 15) Zs[f] = fmaf(fmaf(fmaf(a3, 0.5f, a2), 0.5f, a1), 0.5f, a0);
    }
    __syncthreads();

    // ---- pack pair tables ----
    for (int t = threadIdx.x; t < 31 * 3; t += 128) {
        const int J = t / 3, kh = t - J * 3;
        float4 c0 = scal[J * 9 + kh * 3 + 0];
        float4 c1 = scal[J * 9 + kh * 3 + 1];
        float4 c2 = scal[J * 9 + kh * 3 + 2];
        pA01[t] = make_float4(c0.x, c1.x, c0.y, c1.y);
        {
            __half2 h2 = __floats2half2_rn(c0.z, c1.z);
            __half2 h3 = __floats2half2_rn(c0.w, c1.w);
            pA23[t] = make_uint2(*reinterpret_cast<unsigned*>(&h2),
                                 *reinterpret_cast<unsigned*>(&h3));
        }
        pB01[t] = make_float4(c1.x, c2.x, c1.y, c2.y);
        {
            __half2 h2 = __floats2half2_rn(c1.z, c2.z);
            __half2 h3 = __floats2half2_rn(c1.w, c2.w);
            pB23[t] = make_uint2(*reinterpret_cast<unsigned*>(&h2),
                                 *reinterpret_cast<unsigned*>(&h3));
        }
    }
    __syncthreads();

    float Z[9];
    #pragma unroll
    for (int f = 0; f < 9; f++) Z[f] = Zs[f];

    const float* xcol = x   + img * 4096 + lane * 2;
    float*       ocol = out + img * 4096 + lane * 2;

    float accE[3] = {0.f, 0.f, 0.f};
    float accO[3] = {0.f, 0.f, 0.f};

    // scalar send eval: full fp32 cubic (LDS.128 + 3 FMA)
    auto evalS = [&](int J9, int f, float u) {
        float4 c = scal[J9 + f];
        float t = fmaf(c.w, u, c.z);
        t = fmaf(t, u, c.y);
        return fmaf(t, u, c.x);
    };

    auto row = [&](auto rc) {
        constexpr int r = rc.value;
        const int py = y0 - 1 + r;
        float2 p;
        if constexpr (r == 0 || r == NROWS - 1) {
            p = make_float2(0.f, 0.f);
            if (py >= 0 && py < 64) p = *(const float2*)(xcol + py * 64);
        } else {
            p = *(const float2*)(xcol + py * 64);
        }

        // cell locate with clamp into [0, 31)
        float xce = fminf(fmaxf(fmaf(p.x, 2.5f, 15.5f), 0.f), 30.999f);
        float jfe = floorf(xce);
        const float ue = xce - jfe;
        const int  je  = (int)jfe;
        float xco = fminf(fmaxf(fmaf(p.y, 2.5f, 15.5f), 0.f), 30.999f);
        float jfo = floorf(xco);
        const float uo = xco - jfo;
        const int  jo  = (int)jfo;

        const __half2 u2e = __float2half2_rn(ue);
        const __half2 u2o = __float2half2_rn(uo);
        const int je3 = je * 3, jo3 = jo * 3;
        const int je9 = je * 9, jo9 = jo * 9;

        // out = py+1-kh in strip => kh in [r-3, r] ∩ [0,2]
        constexpr int kh_lo = (r > 3) ? (r - 3) : 0;
        constexpr int kh_hi = (r < 2) ? r : 2;
        #pragma unroll
        for (int kh = kh_lo; kh <= kh_hi; kh++) {
            // even pixel pair: f=3kh -> accO, f=3kh+1 -> accE
            {
                float4 c01 = pA01[je3 + kh];
                uint2  c23 = pA23[je3 + kh];
                __half2 th = __hfma2(*reinterpret_cast<__half2*>(&c23.y), u2e,
                                     *reinterpret_cast<__half2*>(&c23.x));
                float2 t = __half22float2(th);
                accO[2 - kh] += fmaf(fmaf(t.x, ue, c01.z), ue, c01.x);
                accE[2 - kh] += fmaf(fmaf(t.y, ue, c01.w), ue, c01.y);
            }
            // odd pixel pair: f=3kh+1 -> accO, f=3kh+2 -> accE
            {
                float4 c01 = pB01[jo3 + kh];
                uint2  c23 = pB23[jo3 + kh];
                __half2 th = __hfma2(*reinterpret_cast<__half2*>(&c23.y), u2o,
                                     *reinterpret_cast<__half2*>(&c23.x));
                float2 t = __half22float2(th);
                accO[2 - kh] += fmaf(fmaf(t.x, uo, c01.z), uo, c01.x);
                accE[2 - kh] += fmaf(fmaf(t.y, uo, c01.w), uo, c01.y);
            }
            float sL = evalS(je9, kh * 3 + 2, ue);   // even px -> lane-1 odd col
            float sR = evalS(jo9, kh * 3 + 0, uo);   // odd  px -> lane+1 even col

            float rl = __shfl_down_sync(0xffffffffu, sL, 1);
            if (lane == 31) rl = Z[kh * 3 + 2];      // col 64 padding -> out col 63
            float rr = __shfl_up_sync(0xffffffffu, sR, 1);
            if (lane == 0)  rr = Z[kh * 3 + 0];      // col -1 padding -> out col 0
            accO[2 - kh] += rl;
            accE[2 - kh] += rr;
        }

        if constexpr (r >= 2) {
            *(float2*)(ocol + (y0 + r - 2) * 64) = make_float2(accE[0], accO[0]);
        }
        accE[0] = accE[1]; accE[1] = accE[2]; accE[2] = 0.f;
        accO[0] = accO[1]; accO[1] = accO[2]; accO[2] = 0.f;
    };

    row(IC<0>{}); row(IC<1>{}); row(IC<2>{});
    row(IC<3>{}); row(IC<4>{}); row(IC<5>{});
}

extern "C" void kernel_launch(void* const* d_in, const int* in_sizes, int n_in,
                              void* d_out, int out_size) {
    const float* x  = (const float*)d_in[0];  // (8,32,64,64)
    const float* bw = (const float*)d_in[1];  // (1,9)
    const float* sw = (const float*)d_in[2];  // (1,9,8)
    const float* ss = (const float*)d_in[3];  // (1,9)
    float* out = (float*)d_out;

    // 256 images x 16 strips, 4 warp-strips per block
    kan_conv_kernel<<<1024, 128>>>(x, bw, sw, ss, out);
}

// round 14
// speedup vs baseline: 1.2756x; 1.2756x over previous
#include <cuda_runtime.h>
#include <cuda_bf16.h>
#include <cuda_fp16.h>

#define R_ROWS 4
#define NROWS  (R_ROWS + 2)

template<int N> struct IC { static constexpr int value = N; };

// silu via fast approx: v * rcp(1 + 2^(-v*log2e))
__device__ __forceinline__ float fast_silu(float v) {
    float e, r;
    asm("ex2.approx.f32 %0, %1;" : "=f"(e) : "f"(v * -1.442695041f));
    asm("rcp.approx.f32 %0, %1;" : "=f"(r) : "f"(1.0f + e));
    return v * r;
}

// Cubic coeffs of spline_f on cell j (j=11 -> all zero row):
// a0=(W0+4W1+W2)/6, a1=(W2-W0)/2, a2=(W0-2W1+W2)/2, a3=(W3-W0+3(W1-W2))/6
__device__ __forceinline__ void spline_coeffs(int j, int f,
                                              const float* __restrict__ sw,
                                              const float* __restrict__ ss,
                                              float a[4]) {
    a[0] = a[1] = a[2] = a[3] = 0.f;
    if (j < 11) {
        float scale = __ldg(&ss[f]);
        float W[4];
        #pragma unroll
        for (int c = 0; c < 4; c++) {
            int bi = j + c - 3;
            W[c] = (bi >= 0 && bi < 8) ? __ldg(&sw[f * 8 + bi]) * scale : 0.f;
        }
        const float S = 1.f / 6.f;
        a[0] = (W[0] + 4.f * W[1] + W[2]) * S;
        a[1] = (W[2] - W[0]) * 0.5f;
        a[2] = (W[0] - 2.f * W[1] + W[2]) * 0.5f;
        a[3] = (W[3] - W[0] + 3.f * (W[1] - W[2])) * S;
    }
}

// KAN 3x3 conv, shared KANLinear(9->1), cubic B-spline on uniform grid.
// R12 skeleton (warp-per-strip rolling, R=4, kh-trim) + half2-PAIR Horner:
// the 4 accumulator-bound evals per kh collapse into 2 LDS.128 + 6 HFMA2
// + 1 HADD2 + 1 CVT pair; send evals stay scalar fp16-table. LDS bytes
// per pixel unchanged vs R12 (144 B/row), instructions ~-22%.
__global__ __launch_bounds__(128, 7)
void kan_conv_kernel(const float* __restrict__ x,
                     const float* __restrict__ bw,
                     const float* __restrict__ sw,
                     const float* __restrict__ ss,
                     float* __restrict__ out)
{
    __shared__ uint2 polyH[12 * 9];   // scalar send table: [j][f] = {h2(a0,a1), h2(a2,a3)}
    __shared__ uint4 pairE[12 * 3];   // even px pair (lo=f3kh ->accO, hi=f3kh+1 ->accE): 4x half2
    __shared__ uint4 pairO[12 * 3];   // odd  px pair (lo=f3kh+1->accO, hi=f3kh+2 ->accE)
    __shared__ float Zs[9];           // spline value at padding pixels (x=0)

    const int lane  = threadIdx.x & 31;
    const int warp  = threadIdx.x >> 5;
    const int img   = blockIdx.x >> 2;                  // 1024 blocks = 256 images x 4
    const int strip = ((blockIdx.x & 3) << 2) | warp;   // 0..15
    const int y0    = strip * R_ROWS;

    // ---- scalar send table + padding constants ----
    if (threadIdx.x < 108) {
        const int t = threadIdx.x;
        const int j = t / 9, f = t - j * 9;
        float a[4];
        spline_coeffs(j, f, sw, ss, a);
        __half2 h01 = __floats2half2_rn(a[0], a[1]);
        __half2 h23 = __floats2half2_rn(a[2], a[3]);
        uint2 e;
        e.x = *reinterpret_cast<unsigned*>(&h01);
        e.y = *reinterpret_cast<unsigned*>(&h23);
        polyH[t] = e;
        if (j == 5)   // x=0 -> cell 5, u=0.5, silu=0 (fp32 exact)
            Zs[f] = fmaf(fmaf(fmaf(a[3], 0.5f, a[2]), 0.5f, a[1]), 0.5f, a[0]);
    }
    // ---- packed pair tables ----
    if (threadIdx.x < 72) {
        const int which = threadIdx.x / 36;        // 0 = even pair, 1 = odd pair
        const int e = threadIdx.x % 36;
        const int j = e / 3, kh = e - j * 3;
        const int flo = kh * 3 + which;
        float clo[4], chi[4];
        spline_coeffs(j, flo,     sw, ss, clo);
        spline_coeffs(j, flo + 1, sw, ss, chi);
        uint4 q;
        __half2 h0 = __floats2half2_rn(clo[0], chi[0]);
        __half2 h1 = __floats2half2_rn(clo[1], chi[1]);
        __half2 h2 = __floats2half2_rn(clo[2], chi[2]);
        __half2 h3 = __floats2half2_rn(clo[3], chi[3]);
        q.x = *reinterpret_cast<unsigned*>(&h0);
        q.y = *reinterpret_cast<unsigned*>(&h1);
        q.z = *reinterpret_cast<unsigned*>(&h2);
        q.w = *reinterpret_cast<unsigned*>(&h3);
        (which ? pairO : pairE)[j * 3 + kh] = q;
    }
    float bwr[9];
    #pragma unroll
    for (int f = 0; f < 9; f++) bwr[f] = __ldg(&bw[f]);
    __syncthreads();

    float Z[9];
    #pragma unroll
    for (int f = 0; f < 9; f++) Z[f] = Zs[f];

    const float* xcol = x   + img * 4096 + lane * 2;
    float*       ocol = out + img * 4096 + lane * 2;

    float accE[3] = {0.f, 0.f, 0.f};
    float accO[3] = {0.f, 0.f, 0.f};

    // scalar send eval (fp16 coeffs, fp32 Horner, base folded)
    auto evalS = [&](int jbase, float u, float s, int f) {
        uint2 pk = polyH[jbase + f];
        float2 c01 = __half22float2(*reinterpret_cast<__half2*>(&pk.x));
        float2 c23 = __half22float2(*reinterpret_cast<__half2*>(&pk.y));
        float t = fmaf(c23.y, u, c23.x);
        t = fmaf(t, u, c01.y);
        t = fmaf(t, u, c01.x);
        return fmaf(s, bwr[f], t);
    };
    // pair eval: half2 Horner, 2 features at once
    auto evalP = [](const uint4& q, __half2 u2) -> __half2 {
        __half2 t = __hfma2(*reinterpret_cast<const __half2*>(&q.w), u2,
                            *reinterpret_cast<const __half2*>(&q.z));
        t = __hfma2(t, u2, *reinterpret_cast<const __half2*>(&q.y));
        t = __hfma2(t, u2, *reinterpret_cast<const __half2*>(&q.x));
        return t;
    };

    auto row = [&](auto rc) {
        constexpr int r = rc.value;
        const int py = y0 - 1 + r;
        float2 p;
        if constexpr (r == 0 || r == NROWS - 1) {
            p = make_float2(0.f, 0.f);
            if (py >= 0 && py < 64) p = *(const float2*)(xcol + py * 64);
        } else {
            p = *(const float2*)(xcol + py * 64);
        }

        const float se = fast_silu(p.x);
        const float so = fast_silu(p.y);

        // cell locate; out-of-grid -> row 11 (all-zero coeffs, u irrelevant)
        float xce = fmaf(p.x, 2.5f, 5.5f);          // (v+2.2)/0.4
        float jfe = floorf(xce);
        const float ue = xce - jfe;
        const int je = min((unsigned)(int)jfe, 11u);
        float xco = fmaf(p.y, 2.5f, 5.5f);
        float jfo = floorf(xco);
        const float uo = xco - jfo;
        const int jo = min((unsigned)(int)jfo, 11u);

        const __half2 u2e = __float2half2_rn(ue);
        const __half2 u2o = __float2half2_rn(uo);
        const int je3 = je * 3, jo3 = jo * 3;
        const int je9 = je * 9, jo9 = jo * 9;

        // out = py+1-kh in strip => kh in [r-3, r] ∩ [0,2]
        constexpr int kh_lo = (r > 3) ? (r - 3) : 0;
        constexpr int kh_hi = (r < 2) ? r : 2;
        #pragma unroll
        for (int kh = kh_lo; kh <= kh_hi; kh++) {
            __half2 spe = evalP(pairE[je3 + kh], u2e);
            __half2 spo = evalP(pairO[jo3 + kh], u2o);
            float2 sp = __half22float2(__hadd2(spe, spo));

            float aO = accO[2 - kh] + sp.x;          // spline (accO half)
            aO = fmaf(se, bwr[kh * 3 + 0], aO);      // even px base, kw0
            aO = fmaf(so, bwr[kh * 3 + 1], aO);      // odd  px base, kw1
            float aE = accE[2 - kh] + sp.y;          // spline (accE half)
            aE = fmaf(se, bwr[kh * 3 + 1], aE);      // even px base, kw1
            aE = fmaf(so, bwr[kh * 3 + 2], aE);      // odd  px base, kw2

            float sL = evalS(je9, ue, se, kh * 3 + 2);   // even px -> lane-1 odd col
            float sR = evalS(jo9, uo, so, kh * 3 + 0);   // odd  px -> lane+1 even col
            float rl = __shfl_down_sync(0xffffffffu, sL, 1);
            if (lane == 31) rl = Z[kh * 3 + 2];          // col 64 padding -> out col 63
            float rr = __shfl_up_sync(0xffffffffu, sR, 1);
            if (lane == 0)  rr = Z[kh * 3 + 0];          // col -1 padding -> out col 0

            accO[2 - kh] = aO + rl;
            accE[2 - kh] = aE + rr;
        }

        if constexpr (r >= 2) {
            *(float2*)(ocol + (y0 + r - 2) * 64) = make_float2(accE[0], accO[0]);
        }
        accE[0] = accE[1]; accE[1] = accE[2]; accE[2] = 0.f;
        accO[0] = accO[1]; accO[1] = accO[2]; accO[2] = 0.f;
    };

    row(IC<0>{}); row(IC<1>{}); row(IC<2>{});
    row(IC<3>{}); row(IC<4>{}); row(IC<5>{});
}

extern "C" void kernel_launch(void* const* d_in, const int* in_sizes, int n_in,
                              void* d_out, int out_size) {
    const float* x  = (const float*)d_in[0];  // (8,32,64,64)
    const float* bw = (const float*)d_in[1];  // (1,9)
    const float* sw = (const float*)d_in[2];  // (1,9,8)
    const float* ss = (const float*)d_in[3];  // (1,9)
    float* out = (float*)d_out;

    // 256 images x 16 strips, 4 warp-strips per block
    kan_conv_kernel<<<1024, 128>>>(x, bw, sw, ss, out);
}